// round 1
// baseline (speedup 1.0000x reference)
#include <cuda_runtime.h>
#include <cstdint>

// Problem constants
#define B_   32
#define S_   2048
#define D_   1024
#define M_   (B_ * S_)     // 65536
#define NCB  8             // number of 128-wide column blocks over D

// Scratch (device globals; allocation-free rule)
__device__ float g_target2[B_ * D_];          // x@W_in^T + b_c
__device__ float g_score_part[NCB * M_];      // partial scores per column block
__device__ float g_wpart[16 * B_ * D_];       // weighted partials per s-chunk
__device__ float g_weighted[B_ * D_];         // reduced weighted

// ---------------------------------------------------------------------------
// Kernel 1: target2[b][j] = sum_k x[b][k] * W_in[j][k] + b_c[j]
// grid 128 blocks x 256 threads; thread = (b = tid>>3, jj = tid&7)
// ---------------------------------------------------------------------------
__global__ __launch_bounds__(256) void target_kernel(
    const float* __restrict__ x, const float* __restrict__ W_in,
    const float* __restrict__ b_c)
{
    __shared__ float sx[32][129];
    __shared__ float sw[8][129];
    int tid = threadIdx.x;
    int b = tid >> 3, jj = tid & 7;
    int j = blockIdx.x * 8 + jj;
    float acc = 0.f;
    for (int k0 = 0; k0 < D_; k0 += 128) {
        #pragma unroll
        for (int i = 0; i < 16; i++) {
            int f = tid + i * 256;
            int r = f >> 7, c = f & 127;
            sx[r][c] = x[r * D_ + k0 + c];
        }
        #pragma unroll
        for (int i = 0; i < 4; i++) {
            int f = tid + i * 256;
            int r = f >> 7, c = f & 127;
            sw[r][c] = W_in[(size_t)(blockIdx.x * 8 + r) * D_ + k0 + c];
        }
        __syncthreads();
        #pragma unroll 8
        for (int k = 0; k < 128; k++) acc += sx[b][k] * sw[jj][k];
        __syncthreads();
    }
    g_target2[b * D_ + j] = acc + b_c[j];
}

// ---------------------------------------------------------------------------
// Kernel 2: the big fused GEMM.
//   acc[m][n] = context_flat[m][:] . W_c[n][:]   (M=65536, N=1024, K=1024)
//   epilogue: p[m] += sum_n tanh(acc + target2[b][n]) * w_v[n]  per col-block
// Block tile 128x128, BK=32, 256 threads, 8x8 per thread.
// ---------------------------------------------------------------------------
#define BM 128
#define BN 128
#define BK 32
#define TM 8
#define TN 8

__global__ __launch_bounds__(256) void score_gemm_kernel(
    const float* __restrict__ A,     // context [M_, D_]
    const float* __restrict__ Bmat,  // W_c [D_, D_]
    const float* __restrict__ w_v)
{
    __shared__ float As[BK][BM];
    __shared__ float Bs[BK][BN];
    __shared__ float sred[BM][16];

    const int bn = blockIdx.x;   // 0..7
    const int bm = blockIdx.y;   // 0..511
    const int tid = threadIdx.x;
    const int tx = tid & 15, ty = tid >> 4;

    const float* Ab = A + (size_t)bm * BM * D_;
    const float* Bb = Bmat + (size_t)bn * BN * D_;

    float acc[TM][TN];
    #pragma unroll
    for (int i = 0; i < TM; i++)
        #pragma unroll
        for (int j = 0; j < TN; j++) acc[i][j] = 0.f;

    for (int k0 = 0; k0 < D_; k0 += BK) {
        // 128 rows x 32 k = 1024 float4; 4 per thread
        #pragma unroll
        for (int i = 0; i < 4; i++) {
            int f = tid + i * 256;
            int row = f >> 3;            // /8
            int kc = (f & 7) * 4;
            float4 v = *reinterpret_cast<const float4*>(Ab + (size_t)row * D_ + k0 + kc);
            As[kc + 0][row] = v.x; As[kc + 1][row] = v.y;
            As[kc + 2][row] = v.z; As[kc + 3][row] = v.w;
        }
        #pragma unroll
        for (int i = 0; i < 4; i++) {
            int f = tid + i * 256;
            int row = f >> 3;
            int kc = (f & 7) * 4;
            float4 v = *reinterpret_cast<const float4*>(Bb + (size_t)row * D_ + k0 + kc);
            Bs[kc + 0][row] = v.x; Bs[kc + 1][row] = v.y;
            Bs[kc + 2][row] = v.z; Bs[kc + 3][row] = v.w;
        }
        __syncthreads();
        #pragma unroll
        for (int k = 0; k < BK; k++) {
            float ra[TM], rb[TN];
            #pragma unroll
            for (int i = 0; i < TM; i++) ra[i] = As[k][ty * TM + i];
            #pragma unroll
            for (int j = 0; j < TN; j++) rb[j] = Bs[k][tx * TN + j];
            #pragma unroll
            for (int i = 0; i < TM; i++)
                #pragma unroll
                for (int j = 0; j < TN; j++)
                    acc[i][j] += ra[i] * rb[j];
        }
        __syncthreads();
    }

    // epilogue: tanh(acc + target2) . w_v, reduce over the 128 cols of this block
    const int b = (bm * BM) / S_;
    float tgt[TN], wv[TN];
    #pragma unroll
    for (int j = 0; j < TN; j++) {
        int n = bn * BN + tx * TN + j;
        tgt[j] = g_target2[b * D_ + n];
        wv[j] = w_v[n];
    }
    #pragma unroll
    for (int i = 0; i < TM; i++) {
        float s = 0.f;
        #pragma unroll
        for (int j = 0; j < TN; j++)
            s += tanhf(acc[i][j] + tgt[j]) * wv[j];
        sred[ty * TM + i][tx] = s;
    }
    __syncthreads();
    if (tid < BM) {
        float s = 0.f;
        #pragma unroll
        for (int t = 0; t < 16; t++) s += sred[tid][t];
        g_score_part[(size_t)bn * M_ + bm * BM + tid] = s;
    }
}

// ---------------------------------------------------------------------------
// Kernel 3: softmax over S per batch. grid = 32 blocks x 1024 threads.
// attn_w written to d_out + B_*D_.
// ---------------------------------------------------------------------------
__global__ __launch_bounds__(1024) void softmax_kernel(float* __restrict__ attn_out)
{
    __shared__ float red[1024];
    const int b = blockIdx.x;
    const int tid = threadIdx.x;

    float s0 = 0.f, s1 = 0.f;
    #pragma unroll
    for (int p = 0; p < NCB; p++) {
        s0 += g_score_part[(size_t)p * M_ + b * S_ + tid];
        s1 += g_score_part[(size_t)p * M_ + b * S_ + 1024 + tid];
    }
    float m = fmaxf(s0, s1);
    red[tid] = m;
    __syncthreads();
    for (int st = 512; st > 0; st >>= 1) {
        if (tid < st) red[tid] = fmaxf(red[tid], red[tid + st]);
        __syncthreads();
    }
    m = red[0];
    __syncthreads();
    float e0 = expf(s0 - m), e1 = expf(s1 - m);
    red[tid] = e0 + e1;
    __syncthreads();
    for (int st = 512; st > 0; st >>= 1) {
        if (tid < st) red[tid] += red[tid + st];
        __syncthreads();
    }
    float inv = 1.f / red[0];
    attn_out[b * S_ + tid] = e0 * inv;
    attn_out[b * S_ + 1024 + tid] = e1 * inv;
}

// ---------------------------------------------------------------------------
// Kernel 4: weighted partials. grid (16 s-chunks, 32 b) x 256 threads.
// ---------------------------------------------------------------------------
__global__ __launch_bounds__(256) void weighted_kernel(
    const float* __restrict__ context, const float* __restrict__ attn)
{
    const int sc = blockIdx.x;   // 0..15
    const int b = blockIdx.y;    // 0..31
    const int tid = threadIdx.x;
    float acc0 = 0.f, acc1 = 0.f, acc2 = 0.f, acc3 = 0.f;
    const float* ctx = context + ((size_t)b * S_ + sc * 128) * D_;
    const float* aw = attn + b * S_ + sc * 128;
    for (int s = 0; s < 128; s++) {
        float w = aw[s];
        const float* row = ctx + (size_t)s * D_;
        acc0 += w * row[tid];
        acc1 += w * row[tid + 256];
        acc2 += w * row[tid + 512];
        acc3 += w * row[tid + 768];
    }
    float* dst = g_wpart + ((size_t)sc * B_ + b) * D_;
    dst[tid] = acc0; dst[tid + 256] = acc1;
    dst[tid + 512] = acc2; dst[tid + 768] = acc3;
}

// ---------------------------------------------------------------------------
// Kernel 4b: reduce 16 weighted partials.
// ---------------------------------------------------------------------------
__global__ __launch_bounds__(256) void wreduce_kernel()
{
    int idx = blockIdx.x * 256 + threadIdx.x;   // 0..32767
    float s = 0.f;
    #pragma unroll
    for (int p = 0; p < 16; p++) s += g_wpart[(size_t)p * (B_ * D_) + idx];
    g_weighted[idx] = s;
}

// ---------------------------------------------------------------------------
// Kernel 5: h_tilde[b][j] = tanh( [weighted, x][b][:] . W_out[j][:] )
// grid 128 blocks x 256 threads; thread = (b = tid>>3, jj = tid&7)
// ---------------------------------------------------------------------------
__global__ __launch_bounds__(256) void out_kernel(
    const float* __restrict__ x, const float* __restrict__ W_out,
    float* __restrict__ out)
{
    __shared__ float sc[32][129];
    __shared__ float sw[8][129];
    int tid = threadIdx.x;
    int b = tid >> 3, jj = tid & 7;
    int j = blockIdx.x * 8 + jj;
    float acc = 0.f;
    for (int k0 = 0; k0 < 2 * D_; k0 += 128) {
        #pragma unroll
        for (int i = 0; i < 16; i++) {
            int f = tid + i * 256;
            int r = f >> 7, c = f & 127;
            int k = k0 + c;
            sc[r][c] = (k < D_) ? g_weighted[r * D_ + k] : x[r * D_ + (k - D_)];
        }
        #pragma unroll
        for (int i = 0; i < 4; i++) {
            int f = tid + i * 256;
            int r = f >> 7, c = f & 127;
            sw[r][c] = W_out[(size_t)(blockIdx.x * 8 + r) * (2 * D_) + k0 + c];
        }
        __syncthreads();
        #pragma unroll 8
        for (int k = 0; k < 128; k++) acc += sc[b][k] * sw[jj][k];
        __syncthreads();
    }
    out[b * D_ + j] = tanhf(acc);
}

// ---------------------------------------------------------------------------
// Launch
// Inputs (metadata order): x, context, W_in, W_c, b_c, w_v, W_out
// Output: h_tilde [32,1024] then attn_w [32,2048]
// ---------------------------------------------------------------------------
extern "C" void kernel_launch(void* const* d_in, const int* in_sizes, int n_in,
                              void* d_out, int out_size)
{
    const float* x       = (const float*)d_in[0];
    const float* context = (const float*)d_in[1];
    const float* W_in    = (const float*)d_in[2];
    const float* W_c     = (const float*)d_in[3];
    const float* b_c     = (const float*)d_in[4];
    const float* w_v     = (const float*)d_in[5];
    const float* W_out   = (const float*)d_in[6];
    float* out = (float*)d_out;
    float* attn_out = out + B_ * D_;   // attn_w region

    target_kernel<<<128, 256>>>(x, W_in, b_c);
    score_gemm_kernel<<<dim3(NCB, M_ / BM), 256>>>(context, W_c, w_v);
    softmax_kernel<<<B_, 1024>>>(attn_out);
    weighted_kernel<<<dim3(16, B_), 256>>>(context, attn_out);
    wreduce_kernel<<<(B_ * D_) / 256, 256>>>();
    out_kernel<<<128, 256>>>(x, W_out, out);
}

// round 3
// speedup vs baseline: 3.6545x; 3.6545x over previous
#include <cuda_runtime.h>
#include <cstdint>

// Problem constants
#define B_   32
#define S_   2048
#define D_   1024
#define M_   (B_ * S_)     // 65536
#define NCB  8             // 128-wide column blocks over D

// GEMM tiling
#define BM   128
#define BN   128
#define BKF  32            // K floats per pipeline step (128-byte rows)
#define NKS  (D_ / BKF)    // 32 steps

// Scratch (device globals; allocation-free rule)
__device__ float g_target2[B_ * D_];
__device__ float g_score_part[NCB * M_];
__device__ float g_wpart[16 * B_ * D_];
__device__ float g_weighted[B_ * D_];

// ---------------------------------------------------------------------------
// PTX helpers (target-generic: sm_80+ only, NO tcgen05)
// ---------------------------------------------------------------------------
__device__ __forceinline__ uint32_t smem_u32(const void* p) {
    uint32_t a;
    asm("{ .reg .u64 t; cvta.to.shared.u64 t, %1; cvt.u32.u64 %0, t; }"
        : "=r"(a) : "l"(p));
    return a;
}

__device__ __forceinline__ void cp16(uint32_t saddr, const void* gaddr) {
    asm volatile("cp.async.cg.shared.global [%0], [%1], 16;"
                 :: "r"(saddr), "l"(gaddr));
}

__device__ __forceinline__ void ldm4(uint32_t addr, uint32_t& r0, uint32_t& r1,
                                     uint32_t& r2, uint32_t& r3) {
    asm volatile("ldmatrix.sync.aligned.m8n8.x4.shared.b16 {%0,%1,%2,%3}, [%4];"
                 : "=r"(r0), "=r"(r1), "=r"(r2), "=r"(r3) : "r"(addr));
}

__device__ __forceinline__ uint32_t cvt_tf32(uint32_t x) {
    uint32_t y;
    asm("cvt.rna.tf32.f32 %0, %1;" : "=r"(y) : "r"(x));
    return y;
}

__device__ __forceinline__ void mma_tf32(float* d, const uint32_t* a, const uint32_t* b) {
    asm volatile(
        "mma.sync.aligned.m16n8k8.row.col.f32.tf32.tf32.f32 "
        "{%0,%1,%2,%3}, {%4,%5,%6,%7}, {%8,%9}, {%0,%1,%2,%3};"
        : "+f"(d[0]), "+f"(d[1]), "+f"(d[2]), "+f"(d[3])
        : "r"(a[0]), "r"(a[1]), "r"(a[2]), "r"(a[3]), "r"(b[0]), "r"(b[1]));
}

__device__ __forceinline__ float fast_tanh(float x) {
    float y;
    asm("tanh.approx.f32 %0, %1;" : "=f"(y) : "f"(x));
    return y;
}

// ---------------------------------------------------------------------------
// Kernel 1: target2[b][j] = sum_k x[b][k] * W_in[j][k] + b_c[j]
// ---------------------------------------------------------------------------
__global__ __launch_bounds__(256) void target_kernel(
    const float* __restrict__ x, const float* __restrict__ W_in,
    const float* __restrict__ b_c)
{
    __shared__ float sx[32][129];
    __shared__ float sw[8][129];
    int tid = threadIdx.x;
    int b = tid >> 3, jj = tid & 7;
    int j = blockIdx.x * 8 + jj;
    float acc = 0.f;
    for (int k0 = 0; k0 < D_; k0 += 128) {
        #pragma unroll
        for (int i = 0; i < 16; i++) {
            int f = tid + i * 256;
            int r = f >> 7, c = f & 127;
            sx[r][c] = x[r * D_ + k0 + c];
        }
        #pragma unroll
        for (int i = 0; i < 4; i++) {
            int f = tid + i * 256;
            int r = f >> 7, c = f & 127;
            sw[r][c] = W_in[(size_t)(blockIdx.x * 8 + r) * D_ + k0 + c];
        }
        __syncthreads();
        #pragma unroll 8
        for (int k = 0; k < 128; k++) acc += sx[b][k] * sw[jj][k];
        __syncthreads();
    }
    g_target2[b * D_ + j] = acc + b_c[j];
}

// ---------------------------------------------------------------------------
// Kernel 2: tf32 mma.sync score GEMM (128x128 tile) + fused tanh.w_v epilogue
// ---------------------------------------------------------------------------
// smem layout (relative to 1024-aligned base):
//   0     : s_tgt[128]
//   512   : s_wv[128]
//   1024  : s_red[128*4]
//   4096  : A0 (16KB) | 20480: B0 | 36864: A1 | 53248: B1
#define OFF_TILE   4096
#define STAGE_STRIDE 32768
#define SMEM_NEED  (4096 + 2 * STAGE_STRIDE)
#define SMEM_BYTES (SMEM_NEED + 1024)

__device__ __forceinline__ void cp_tiles(
    const float* __restrict__ Ag, const float* __restrict__ Bg,
    int step, uint32_t sA, uint32_t sB, int tid)
{
    const int kf = step * BKF;
    #pragma unroll
    for (int i = 0; i < 4; i++) {
        int f = tid + i * 256;
        int row = f >> 3, kq = f & 7;
        uint32_t off = (uint32_t)(row * 128 + kq * 16) ^ (((uint32_t)(row & 7)) << 4);
        cp16(sA + off, Ag + (size_t)row * D_ + kf + kq * 4);
    }
    #pragma unroll
    for (int i = 0; i < 4; i++) {
        int f = tid + i * 256;
        int row = f >> 3, kq = f & 7;
        uint32_t off = (uint32_t)(row * 128 + kq * 16) ^ (((uint32_t)(row & 7)) << 4);
        cp16(sB + off, Bg + (size_t)row * D_ + kf + kq * 4);
    }
}

__global__ __launch_bounds__(256) void score_gemm_mma(
    const float* __restrict__ context,
    const float* __restrict__ W_c,
    const float* __restrict__ w_v)
{
    extern __shared__ char dynsmem[];
    uint32_t sbm = smem_u32(dynsmem);
    uint32_t ab = (sbm + 1023u) & ~1023u;
    char* abp = dynsmem + (ab - sbm);

    const int bn = blockIdx.x;       // 0..7
    const int bm = blockIdx.y;       // 0..511
    const int tid = threadIdx.x;
    const int wid = tid >> 5, lid = tid & 31;
    const int warp_m = wid & 1;      // 2 M-rows of warps (64 each)
    const int warp_n = wid >> 1;     // 4 N-cols of warps (32 each)
    const int b = bm >> 4;           // 16 m-blocks per batch

    float* s_tgt = (float*)(abp);
    float* s_wv  = (float*)(abp + 512);
    float* s_red = (float*)(abp + 1024);

    if (tid < 128) {
        s_tgt[tid] = g_target2[b * D_ + bn * BN + tid];
        s_wv[tid]  = w_v[bn * BN + tid];
    }

    const float* Ag = context + (size_t)bm * BM * D_;
    const float* Bg = W_c + (size_t)bn * BN * D_;

    // ldmatrix lane base offsets (within a tile), SW128 swizzle applied
    const int r15 = lid & 15, q = lid >> 4;
    const uint32_t swz = ((uint32_t)(lid & 7)) << 4;
    const uint32_t loffA = (uint32_t)((warp_m * 64 + r15) * 128 + q * 16) ^ swz;
    const uint32_t loffB = (uint32_t)((warp_n * 32 + r15) * 128 + q * 16) ^ swz;

    const uint32_t tbase = ab + OFF_TILE;

    float acc[4][4][4];
    #pragma unroll
    for (int mf = 0; mf < 4; mf++)
        #pragma unroll
        for (int nf = 0; nf < 4; nf++)
            #pragma unroll
            for (int r = 0; r < 4; r++) acc[mf][nf][r] = 0.f;

    // prologue: stage 0
    cp_tiles(Ag, Bg, 0, tbase, tbase + 16384, tid);
    asm volatile("cp.async.commit_group;" ::: "memory");

    for (int ks = 0; ks < NKS; ks++) {
        const uint32_t stage = (uint32_t)(ks & 1) * STAGE_STRIDE;
        if (ks + 1 < NKS) {
            const uint32_t nstage = (uint32_t)((ks + 1) & 1) * STAGE_STRIDE;
            cp_tiles(Ag, Bg, ks + 1, tbase + nstage, tbase + nstage + 16384, tid);
            asm volatile("cp.async.commit_group;" ::: "memory");
            asm volatile("cp.async.wait_group 1;" ::: "memory");
        } else {
            asm volatile("cp.async.wait_group 0;" ::: "memory");
        }
        __syncthreads();

        const uint32_t baseA = tbase + stage;
        const uint32_t baseB = tbase + stage + 16384;

        #pragma unroll
        for (int c = 0; c < 4; c++) {
            uint32_t a[4][4], bb[4][2];
            #pragma unroll
            for (int mf = 0; mf < 4; mf++) {
                uint32_t t0, t1, t2, t3;
                ldm4((baseA + loffA + mf * 2048u) ^ ((uint32_t)c << 5), t0, t1, t2, t3);
                a[mf][0] = cvt_tf32(t0); a[mf][1] = cvt_tf32(t1);
                a[mf][2] = cvt_tf32(t2); a[mf][3] = cvt_tf32(t3);
            }
            #pragma unroll
            for (int p = 0; p < 2; p++) {
                uint32_t t0, t1, t2, t3;
                ldm4((baseB + loffB + p * 2048u) ^ ((uint32_t)c << 5), t0, t1, t2, t3);
                bb[2 * p][0]     = cvt_tf32(t0); bb[2 * p][1]     = cvt_tf32(t2);
                bb[2 * p + 1][0] = cvt_tf32(t1); bb[2 * p + 1][1] = cvt_tf32(t3);
            }
            #pragma unroll
            for (int mf = 0; mf < 4; mf++)
                #pragma unroll
                for (int nf = 0; nf < 4; nf++)
                    mma_tf32(acc[mf][nf], a[mf], bb[nf]);
        }
        __syncthreads();
    }

    // Epilogue: scores partial = sum_n tanh(acc + tgt[n]) * wv[n]
    const int g = lid >> 2, tig = lid & 3;
    #pragma unroll
    for (int mf = 0; mf < 4; mf++) {
        float p0 = 0.f, p1 = 0.f;
        #pragma unroll
        for (int nf = 0; nf < 4; nf++) {
            int n0 = warp_n * 32 + nf * 8 + 2 * tig;
            float t0 = s_tgt[n0], t1 = s_tgt[n0 + 1];
            float v0 = s_wv[n0],  v1 = s_wv[n0 + 1];
            p0 += fast_tanh(acc[mf][nf][0] + t0) * v0;
            p0 += fast_tanh(acc[mf][nf][1] + t1) * v1;
            p1 += fast_tanh(acc[mf][nf][2] + t0) * v0;
            p1 += fast_tanh(acc[mf][nf][3] + t1) * v1;
        }
        // reduce across tig (quad)
        p0 += __shfl_xor_sync(0xFFFFFFFF, p0, 1);
        p0 += __shfl_xor_sync(0xFFFFFFFF, p0, 2);
        p1 += __shfl_xor_sync(0xFFFFFFFF, p1, 1);
        p1 += __shfl_xor_sync(0xFFFFFFFF, p1, 2);
        if (tig == 0) {
            int row = warp_m * 64 + mf * 16 + g;
            s_red[row * 4 + warp_n] = p0;
            s_red[(row + 8) * 4 + warp_n] = p1;
        }
    }
    __syncthreads();
    if (tid < BM) {
        float s = s_red[tid * 4] + s_red[tid * 4 + 1] +
                  s_red[tid * 4 + 2] + s_red[tid * 4 + 3];
        g_score_part[(size_t)bn * M_ + bm * BM + tid] = s;
    }
}

// ---------------------------------------------------------------------------
// Kernel 3: softmax over S per batch
// ---------------------------------------------------------------------------
__global__ __launch_bounds__(1024) void softmax_kernel(float* __restrict__ attn_out)
{
    __shared__ float red[1024];
    const int b = blockIdx.x;
    const int tid = threadIdx.x;

    float s0 = 0.f, s1 = 0.f;
    #pragma unroll
    for (int p = 0; p < NCB; p++) {
        s0 += g_score_part[(size_t)p * M_ + b * S_ + tid];
        s1 += g_score_part[(size_t)p * M_ + b * S_ + 1024 + tid];
    }
    float m = fmaxf(s0, s1);
    red[tid] = m;
    __syncthreads();
    for (int st = 512; st > 0; st >>= 1) {
        if (tid < st) red[tid] = fmaxf(red[tid], red[tid + st]);
        __syncthreads();
    }
    m = red[0];
    __syncthreads();
    float e0 = expf(s0 - m), e1 = expf(s1 - m);
    red[tid] = e0 + e1;
    __syncthreads();
    for (int st = 512; st > 0; st >>= 1) {
        if (tid < st) red[tid] += red[tid + st];
        __syncthreads();
    }
    float inv = 1.f / red[0];
    attn_out[b * S_ + tid] = e0 * inv;
    attn_out[b * S_ + 1024 + tid] = e1 * inv;
}

// ---------------------------------------------------------------------------
// Kernel 4: weighted partials (float4). grid (16 s-chunks, 32 b) x 256
// ---------------------------------------------------------------------------
__global__ __launch_bounds__(256) void weighted_kernel(
    const float* __restrict__ context, const float* __restrict__ attn)
{
    const int sc = blockIdx.x;
    const int b = blockIdx.y;
    const int tid = threadIdx.x;
    float4 acc = make_float4(0.f, 0.f, 0.f, 0.f);
    const float4* ctx4 = (const float4*)(context + ((size_t)b * S_ + sc * 128) * D_);
    const float* aw = attn + b * S_ + sc * 128;
    #pragma unroll 4
    for (int s = 0; s < 128; s++) {
        float w = aw[s];
        float4 v = ctx4[(size_t)s * 256 + tid];
        acc.x += w * v.x; acc.y += w * v.y;
        acc.z += w * v.z; acc.w += w * v.w;
    }
    float4* dst = (float4*)(g_wpart + ((size_t)sc * B_ + b) * D_);
    dst[tid] = acc;
}

__global__ __launch_bounds__(256) void wreduce_kernel()
{
    int i = blockIdx.x * 256 + threadIdx.x;
    float4 s = make_float4(0.f, 0.f, 0.f, 0.f);
    #pragma unroll
    for (int p = 0; p < 16; p++) {
        float4 v = ((const float4*)g_wpart)[(size_t)p * (B_ * D_ / 4) + i];
        s.x += v.x; s.y += v.y; s.z += v.z; s.w += v.w;
    }
    ((float4*)g_weighted)[i] = s;
}

// ---------------------------------------------------------------------------
// Kernel 5: h_tilde = tanh([weighted, x] @ W_out^T)
// ---------------------------------------------------------------------------
__global__ __launch_bounds__(256) void out_kernel(
    const float* __restrict__ x, const float* __restrict__ W_out,
    float* __restrict__ out)
{
    __shared__ float sc[32][129];
    __shared__ float sw[8][129];
    int tid = threadIdx.x;
    int b = tid >> 3, jj = tid & 7;
    int j = blockIdx.x * 8 + jj;
    float acc = 0.f;
    for (int k0 = 0; k0 < 2 * D_; k0 += 128) {
        #pragma unroll
        for (int i = 0; i < 16; i++) {
            int f = tid + i * 256;
            int r = f >> 7, c = f & 127;
            int k = k0 + c;
            sc[r][c] = (k < D_) ? g_weighted[r * D_ + k] : x[r * D_ + (k - D_)];
        }
        #pragma unroll
        for (int i = 0; i < 4; i++) {
            int f = tid + i * 256;
            int r = f >> 7, c = f & 127;
            sw[r][c] = W_out[(size_t)(blockIdx.x * 8 + r) * (2 * D_) + k0 + c];
        }
        __syncthreads();
        #pragma unroll 8
        for (int k = 0; k < 128; k++) acc += sc[b][k] * sw[jj][k];
        __syncthreads();
    }
    out[b * D_ + j] = tanhf(acc);
}

// ---------------------------------------------------------------------------
// Launch. Inputs: x, context, W_in, W_c, b_c, w_v, W_out
// Output: h_tilde [32,1024] then attn_w [32,2048]
// ---------------------------------------------------------------------------
extern "C" void kernel_launch(void* const* d_in, const int* in_sizes, int n_in,
                              void* d_out, int out_size)
{
    const float* x       = (const float*)d_in[0];
    const float* context = (const float*)d_in[1];
    const float* W_in    = (const float*)d_in[2];
    const float* W_c     = (const float*)d_in[3];
    const float* b_c     = (const float*)d_in[4];
    const float* w_v     = (const float*)d_in[5];
    const float* W_out   = (const float*)d_in[6];
    float* out = (float*)d_out;
    float* attn_out = out + B_ * D_;

    static int configured = 0;
    cudaFuncSetAttribute(score_gemm_mma,
                         cudaFuncAttributeMaxDynamicSharedMemorySize, SMEM_BYTES);
    (void)configured;

    target_kernel<<<128, 256>>>(x, W_in, b_c);
    score_gemm_mma<<<dim3(NCB, M_ / BM), 256, SMEM_BYTES>>>(context, W_c, w_v);
    softmax_kernel<<<B_, 1024>>>(attn_out);
    weighted_kernel<<<dim3(16, B_), 256>>>(context, attn_out);
    wreduce_kernel<<<32, 256>>>();
    out_kernel<<<128, 256>>>(x, W_out, out);
}

// round 4
// speedup vs baseline: 6.4876x; 1.7752x over previous
#include <cuda_runtime.h>
#include <cuda_fp16.h>
#include <cstdint>

// Problem constants
#define B_   32
#define S_   2048
#define D_   1024
#define M_   (B_ * S_)     // 65536
#define NCB  8             // 128-wide column blocks over D

// GEMM tiling (fp16 path)
#define BM   128
#define BN   128
#define BKH  64            // K halves per pipeline step (= 128-byte rows)
#define NKS  (D_ / BKH)    // 16 steps
#define NSTAGE 3

// Scratch (device globals; allocation-free rule)
__device__ float  g_target2[B_ * D_];
__device__ float  g_score_part[NCB * M_];
__device__ float  g_wpart[16 * B_ * D_];
__device__ float  g_weighted[B_ * D_];
__device__ __half g_ctx_h[(size_t)M_ * D_];   // 128MB fp16 context
__device__ __half g_wc_h[D_ * D_];            // 2MB fp16 W_c

// ---------------------------------------------------------------------------
// PTX helpers (target-generic; no tcgen05 — bench compiles generic compute_103)
// ---------------------------------------------------------------------------
__device__ __forceinline__ uint32_t smem_u32(const void* p) {
    uint32_t a;
    asm("{ .reg .u64 t; cvta.to.shared.u64 t, %1; cvt.u32.u64 %0, t; }"
        : "=r"(a) : "l"(p));
    return a;
}

__device__ __forceinline__ void cp16(uint32_t saddr, const void* gaddr) {
    asm volatile("cp.async.cg.shared.global [%0], [%1], 16;"
                 :: "r"(saddr), "l"(gaddr));
}

__device__ __forceinline__ void ldm4(uint32_t addr, uint32_t& r0, uint32_t& r1,
                                     uint32_t& r2, uint32_t& r3) {
    asm volatile("ldmatrix.sync.aligned.m8n8.x4.shared.b16 {%0,%1,%2,%3}, [%4];"
                 : "=r"(r0), "=r"(r1), "=r"(r2), "=r"(r3) : "r"(addr));
}

__device__ __forceinline__ void mma_f16(float* d, const uint32_t* a, const uint32_t* b) {
    asm volatile(
        "mma.sync.aligned.m16n8k16.row.col.f32.f16.f16.f32 "
        "{%0,%1,%2,%3}, {%4,%5,%6,%7}, {%8,%9}, {%0,%1,%2,%3};"
        : "+f"(d[0]), "+f"(d[1]), "+f"(d[2]), "+f"(d[3])
        : "r"(a[0]), "r"(a[1]), "r"(a[2]), "r"(a[3]), "r"(b[0]), "r"(b[1]));
}

__device__ __forceinline__ float fast_tanh(float x) {
    float y;
    asm("tanh.approx.f32 %0, %1;" : "=f"(y) : "f"(x));
    return y;
}

// ---------------------------------------------------------------------------
// Kernel 0a/0b: fp16 conversion pre-passes
// ---------------------------------------------------------------------------
__global__ __launch_bounds__(256) void cvt_ctx_kernel(const float* __restrict__ ctx)
{
    size_t i = ((size_t)blockIdx.x * 256 + threadIdx.x) * 4;
    float4 v = *(const float4*)(ctx + i);
    __half2 h0 = __floats2half2_rn(v.x, v.y);
    __half2 h1 = __floats2half2_rn(v.z, v.w);
    uint2 o;
    o.x = *(uint32_t*)&h0;
    o.y = *(uint32_t*)&h1;
    *(uint2*)(g_ctx_h + i) = o;
}

__global__ __launch_bounds__(256) void cvt_wc_kernel(const float* __restrict__ wc)
{
    size_t i = ((size_t)blockIdx.x * 256 + threadIdx.x) * 4;
    float4 v = *(const float4*)(wc + i);
    __half2 h0 = __floats2half2_rn(v.x, v.y);
    __half2 h1 = __floats2half2_rn(v.z, v.w);
    uint2 o;
    o.x = *(uint32_t*)&h0;
    o.y = *(uint32_t*)&h1;
    *(uint2*)(g_wc_h + i) = o;
}

// ---------------------------------------------------------------------------
// Kernel 1: target2[b][j] = sum_k x[b][k] * W_in[j][k] + b_c[j]
// ---------------------------------------------------------------------------
__global__ __launch_bounds__(256) void target_kernel(
    const float* __restrict__ x, const float* __restrict__ W_in,
    const float* __restrict__ b_c)
{
    __shared__ float sx[32][129];
    __shared__ float sw[8][129];
    int tid = threadIdx.x;
    int b = tid >> 3, jj = tid & 7;
    int j = blockIdx.x * 8 + jj;
    float acc = 0.f;
    for (int k0 = 0; k0 < D_; k0 += 128) {
        #pragma unroll
        for (int i = 0; i < 16; i++) {
            int f = tid + i * 256;
            int r = f >> 7, c = f & 127;
            sx[r][c] = x[r * D_ + k0 + c];
        }
        #pragma unroll
        for (int i = 0; i < 4; i++) {
            int f = tid + i * 256;
            int r = f >> 7, c = f & 127;
            sw[r][c] = W_in[(size_t)(blockIdx.x * 8 + r) * D_ + k0 + c];
        }
        __syncthreads();
        #pragma unroll 8
        for (int k = 0; k < 128; k++) acc += sx[b][k] * sw[jj][k];
        __syncthreads();
    }
    g_target2[b * D_ + j] = acc + b_c[j];
}

// ---------------------------------------------------------------------------
// Kernel 2: fp16 mma.sync score GEMM (128x128x64/stage, 3-stage pipeline)
// ---------------------------------------------------------------------------
// smem (from 1024-aligned base):
//   0: s_tgt[128]  512: s_wv[128]  1024: s_red[512]  4096: tiles (3 x 32KB)
#define OFF_TILE     4096
#define STAGE_STRIDE 32768
#define SMEM_NEED    (OFF_TILE + NSTAGE * STAGE_STRIDE)
#define SMEM_BYTES   (SMEM_NEED + 1024)

__device__ __forceinline__ void cp_stage_h(
    const __half* __restrict__ Ag, const __half* __restrict__ Bg,
    int step, uint32_t sA, int tid)
{
    const int kh = step * BKH;
    // A: 128 rows x 8 chunks of 16B -> 4 per thread
    #pragma unroll
    for (int i = 0; i < 4; i++) {
        int f = tid + i * 256;
        int row = f >> 3, kq = f & 7;
        uint32_t off = (uint32_t)(row * 128) + (((uint32_t)kq * 16) ^ (((uint32_t)(row & 7)) << 4));
        cp16(sA + off, Ag + (size_t)row * D_ + kh + kq * 8);
    }
    // B: 128 rows x 8 chunks -> 4 per thread (at sA + 16384)
    #pragma unroll
    for (int i = 0; i < 4; i++) {
        int f = tid + i * 256;
        int row = f >> 3, kq = f & 7;
        uint32_t off = (uint32_t)(row * 128) + (((uint32_t)kq * 16) ^ (((uint32_t)(row & 7)) << 4));
        cp16(sA + 16384 + off, Bg + (size_t)row * D_ + kh + kq * 8);
    }
}

__global__ __launch_bounds__(256, 2) void score_gemm_mma(
    const float* __restrict__ w_v)
{
    extern __shared__ char dynsmem[];
    uint32_t sbm = smem_u32(dynsmem);
    uint32_t ab = (sbm + 1023u) & ~1023u;
    char* abp = dynsmem + (ab - sbm);

    const int bn = blockIdx.x;       // 0..7
    const int bm = blockIdx.y;       // 0..511
    const int tid = threadIdx.x;
    const int wid = tid >> 5, lid = tid & 31;
    const int warp_m = wid & 1;      // 2 M-rows of warps (64 each)
    const int warp_n = wid >> 1;     // 4 N-cols of warps (32 each)
    const int b = bm >> 4;           // 16 m-blocks per batch

    float* s_tgt = (float*)(abp);
    float* s_wv  = (float*)(abp + 512);
    float* s_red = (float*)(abp + 1024);

    if (tid < 128) {
        s_tgt[tid] = g_target2[b * D_ + bn * BN + tid];
        s_wv[tid]  = w_v[bn * BN + tid];
    }

    const __half* Ag = g_ctx_h + (size_t)bm * BM * D_;
    const __half* Bg = g_wc_h + (size_t)bn * BN * D_;

    // ldmatrix lane base offsets (swizzled)
    const int r15 = lid & 15, q = lid >> 4;
    const uint32_t swz = ((uint32_t)(r15 & 7)) << 4;
    const uint32_t loffA = (uint32_t)((warp_m * 64 + r15) * 128) + (((uint32_t)q * 16) ^ swz);
    const uint32_t loffB = (uint32_t)((warp_n * 32 + r15) * 128) + (((uint32_t)q * 16) ^ swz) + 16384u;

    const uint32_t tbase = ab + OFF_TILE;

    float acc[4][4][4];
    #pragma unroll
    for (int mf = 0; mf < 4; mf++)
        #pragma unroll
        for (int nf = 0; nf < 4; nf++)
            #pragma unroll
            for (int r = 0; r < 4; r++) acc[mf][nf][r] = 0.f;

    // prologue: stages 0 and 1
    cp_stage_h(Ag, Bg, 0, tbase, tid);
    asm volatile("cp.async.commit_group;" ::: "memory");
    cp_stage_h(Ag, Bg, 1, tbase + STAGE_STRIDE, tid);
    asm volatile("cp.async.commit_group;" ::: "memory");

    uint32_t stage_off[NSTAGE] = { 0u, STAGE_STRIDE, 2u * STAGE_STRIDE };

    for (int ks = 0; ks < NKS; ks++) {
        asm volatile("cp.async.wait_group 1;" ::: "memory");
        __syncthreads();
        // issue next-next stage load (buffer (ks+2)%3 == (ks-1)%3, reads done)
        if (ks + 2 < NKS)
            cp_stage_h(Ag, Bg, ks + 2, tbase + stage_off[(ks + 2) % 3], tid);
        asm volatile("cp.async.commit_group;" ::: "memory");

        const uint32_t baseA = tbase + stage_off[ks % 3] + loffA;
        const uint32_t baseB = tbase + stage_off[ks % 3] + loffB;

        #pragma unroll
        for (int c = 0; c < 4; c++) {
            uint32_t a[4][4], bb[4][2];
            #pragma unroll
            for (int mf = 0; mf < 4; mf++)
                ldm4((baseA + mf * 2048u) ^ ((uint32_t)c << 5),
                     a[mf][0], a[mf][1], a[mf][2], a[mf][3]);
            #pragma unroll
            for (int p = 0; p < 2; p++) {
                uint32_t t0, t1, t2, t3;
                ldm4((baseB + p * 2048u) ^ ((uint32_t)c << 5), t0, t1, t2, t3);
                bb[2 * p][0]     = t0; bb[2 * p][1]     = t2;
                bb[2 * p + 1][0] = t1; bb[2 * p + 1][1] = t3;
            }
            #pragma unroll
            for (int mf = 0; mf < 4; mf++)
                #pragma unroll
                for (int nf = 0; nf < 4; nf++)
                    mma_f16(acc[mf][nf], a[mf], bb[nf]);
        }
    }

    __syncthreads();

    // Epilogue: partial score = sum_n tanh(acc + tgt[n]) * wv[n]
    const int g = lid >> 2, tig = lid & 3;
    #pragma unroll
    for (int mf = 0; mf < 4; mf++) {
        float p0 = 0.f, p1 = 0.f;
        #pragma unroll
        for (int nf = 0; nf < 4; nf++) {
            int n0 = warp_n * 32 + nf * 8 + 2 * tig;
            float t0 = s_tgt[n0], t1 = s_tgt[n0 + 1];
            float v0 = s_wv[n0],  v1 = s_wv[n0 + 1];
            p0 += fast_tanh(acc[mf][nf][0] + t0) * v0;
            p0 += fast_tanh(acc[mf][nf][1] + t1) * v1;
            p1 += fast_tanh(acc[mf][nf][2] + t0) * v0;
            p1 += fast_tanh(acc[mf][nf][3] + t1) * v1;
        }
        p0 += __shfl_xor_sync(0xFFFFFFFF, p0, 1);
        p0 += __shfl_xor_sync(0xFFFFFFFF, p0, 2);
        p1 += __shfl_xor_sync(0xFFFFFFFF, p1, 1);
        p1 += __shfl_xor_sync(0xFFFFFFFF, p1, 2);
        if (tig == 0) {
            int row = warp_m * 64 + mf * 16 + g;
            s_red[row * 4 + warp_n] = p0;
            s_red[(row + 8) * 4 + warp_n] = p1;
        }
    }
    __syncthreads();
    if (tid < BM) {
        float s = s_red[tid * 4] + s_red[tid * 4 + 1] +
                  s_red[tid * 4 + 2] + s_red[tid * 4 + 3];
        g_score_part[(size_t)bn * M_ + bm * BM + tid] = s;
    }
}

// ---------------------------------------------------------------------------
// Kernel 3: softmax over S per batch
// ---------------------------------------------------------------------------
__global__ __launch_bounds__(1024) void softmax_kernel(float* __restrict__ attn_out)
{
    __shared__ float red[1024];
    const int b = blockIdx.x;
    const int tid = threadIdx.x;

    float s0 = 0.f, s1 = 0.f;
    #pragma unroll
    for (int p = 0; p < NCB; p++) {
        s0 += g_score_part[(size_t)p * M_ + b * S_ + tid];
        s1 += g_score_part[(size_t)p * M_ + b * S_ + 1024 + tid];
    }
    float m = fmaxf(s0, s1);
    red[tid] = m;
    __syncthreads();
    for (int st = 512; st > 0; st >>= 1) {
        if (tid < st) red[tid] = fmaxf(red[tid], red[tid + st]);
        __syncthreads();
    }
    m = red[0];
    __syncthreads();
    float e0 = expf(s0 - m), e1 = expf(s1 - m);
    red[tid] = e0 + e1;
    __syncthreads();
    for (int st = 512; st > 0; st >>= 1) {
        if (tid < st) red[tid] += red[tid + st];
        __syncthreads();
    }
    float inv = 1.f / red[0];
    attn_out[b * S_ + tid] = e0 * inv;
    attn_out[b * S_ + 1024 + tid] = e1 * inv;
}

// ---------------------------------------------------------------------------
// Kernel 4: weighted partials from fp16 context. grid (16, 32) x 256
// ---------------------------------------------------------------------------
__global__ __launch_bounds__(256) void weighted_kernel(const float* __restrict__ attn)
{
    const int sc = blockIdx.x;
    const int b = blockIdx.y;
    const int tid = threadIdx.x;
    float4 acc = make_float4(0.f, 0.f, 0.f, 0.f);
    const uint2* ctx2 = (const uint2*)(g_ctx_h + ((size_t)b * S_ + sc * 128) * D_);
    const float* aw = attn + b * S_ + sc * 128;
    #pragma unroll 4
    for (int s = 0; s < 128; s++) {
        float w = aw[s];
        uint2 v = ctx2[(size_t)s * 256 + tid];
        float2 f0 = __half22float2(*(__half2*)&v.x);
        float2 f1 = __half22float2(*(__half2*)&v.y);
        acc.x += w * f0.x; acc.y += w * f0.y;
        acc.z += w * f1.x; acc.w += w * f1.y;
    }
    float4* dst = (float4*)(g_wpart + ((size_t)sc * B_ + b) * D_);
    dst[tid] = acc;
}

__global__ __launch_bounds__(256) void wreduce_kernel()
{
    int i = blockIdx.x * 256 + threadIdx.x;
    float4 s = make_float4(0.f, 0.f, 0.f, 0.f);
    #pragma unroll
    for (int p = 0; p < 16; p++) {
        float4 v = ((const float4*)g_wpart)[(size_t)p * (B_ * D_ / 4) + i];
        s.x += v.x; s.y += v.y; s.z += v.z; s.w += v.w;
    }
    ((float4*)g_weighted)[i] = s;
}

// ---------------------------------------------------------------------------
// Kernel 5: h_tilde = tanh([weighted, x] @ W_out^T)
// ---------------------------------------------------------------------------
__global__ __launch_bounds__(256) void out_kernel(
    const float* __restrict__ x, const float* __restrict__ W_out,
    float* __restrict__ out)
{
    __shared__ float sc[32][129];
    __shared__ float sw[8][129];
    int tid = threadIdx.x;
    int b = tid >> 3, jj = tid & 7;
    int j = blockIdx.x * 8 + jj;
    float acc = 0.f;
    for (int k0 = 0; k0 < 2 * D_; k0 += 128) {
        #pragma unroll
        for (int i = 0; i < 16; i++) {
            int f = tid + i * 256;
            int r = f >> 7, c = f & 127;
            int k = k0 + c;
            sc[r][c] = (k < D_) ? g_weighted[r * D_ + k] : x[r * D_ + (k - D_)];
        }
        #pragma unroll
        for (int i = 0; i < 4; i++) {
            int f = tid + i * 256;
            int r = f >> 7, c = f & 127;
            sw[r][c] = W_out[(size_t)(blockIdx.x * 8 + r) * (2 * D_) + k0 + c];
        }
        __syncthreads();
        #pragma unroll 8
        for (int k = 0; k < 128; k++) acc += sc[b][k] * sw[jj][k];
        __syncthreads();
    }
    out[b * D_ + j] = tanhf(acc);
}

// ---------------------------------------------------------------------------
// Launch. Inputs: x, context, W_in, W_c, b_c, w_v, W_out
// Output: h_tilde [32,1024] then attn_w [32,2048]
// ---------------------------------------------------------------------------
extern "C" void kernel_launch(void* const* d_in, const int* in_sizes, int n_in,
                              void* d_out, int out_size)
{
    const float* x       = (const float*)d_in[0];
    const float* context = (const float*)d_in[1];
    const float* W_in    = (const float*)d_in[2];
    const float* W_c     = (const float*)d_in[3];
    const float* b_c     = (const float*)d_in[4];
    const float* w_v     = (const float*)d_in[5];
    const float* W_out   = (const float*)d_in[6];
    float* out = (float*)d_out;
    float* attn_out = out + B_ * D_;

    cudaFuncSetAttribute(score_gemm_mma,
                         cudaFuncAttributeMaxDynamicSharedMemorySize, SMEM_BYTES);

    cvt_ctx_kernel<<<(int)((size_t)M_ * D_ / 4 / 256), 256>>>(context);
    cvt_wc_kernel<<<D_ * D_ / 4 / 256, 256>>>(W_c);
    target_kernel<<<128, 256>>>(x, W_in, b_c);
    score_gemm_mma<<<dim3(NCB, M_ / BM), 256, SMEM_BYTES>>>(w_v);
    softmax_kernel<<<B_, 1024>>>(attn_out);
    weighted_kernel<<<dim3(16, B_), 256>>>(attn_out);
    wreduce_kernel<<<32, 256>>>();
    out_kernel<<<128, 256>>>(x, W_out, out);
}